// round 13
// baseline (speedup 1.0000x reference)
#include <cuda_runtime.h>
#include <cuda_fp16.h>
#include <cstdint>

// GIN (N=8192, D=256), 2 layers. fp16 2-pass split-activation HMMA GEMMs.
// R13: single-wave residency — 4 CTAs/SM (launch_bounds + 100% smem carveout)
// so grid 512 fits in one wave (592 slots). Otherwise identical to R12.

#define GN 8192
#define GD 256

// ---------------- scratch (__device__ globals; no allocation allowed) ----------------
__device__ __half g_Ah[GN * GD];
__device__ __half g_Al[GN * GD];
__device__ __half g_Bh[GN * GD];
__device__ __half g_Bl[GN * GD];
__device__ __half g_W1[GD * GD];
__device__ __half g_W2[GD * GD];
__device__ float g_F[GN * GD];

// ---------------- PTX helpers (sm_80-era, compute_103-legal) ----------------
__device__ __forceinline__ uint32_t smem_u32(const void* p) {
    uint32_t a;
    asm("{ .reg .u64 t; cvta.to.shared.u64 t, %1; cvt.u32.u64 %0, t; }"
        : "=r"(a) : "l"(p));
    return a;
}

__device__ __forceinline__ void cp_async16(uint32_t s, const void* g) {
    asm volatile("cp.async.cg.shared.global [%0], [%1], 16;" :: "r"(s), "l"(g));
}
#define CP_COMMIT() asm volatile("cp.async.commit_group;" ::: "memory")
#define CP_WAIT(n)  asm volatile("cp.async.wait_group %0;" :: "n"(n) : "memory")

__device__ __forceinline__ void ldsm_x4(uint32_t* r, uint32_t addr) {
    asm volatile("ldmatrix.sync.aligned.m8n8.x4.shared.b16 {%0,%1,%2,%3}, [%4];"
                 : "=r"(r[0]), "=r"(r[1]), "=r"(r[2]), "=r"(r[3]) : "r"(addr));
}

__device__ __forceinline__ void mma16816(float* d, const uint32_t* a,
                                         const uint32_t* b) {
    asm volatile(
        "mma.sync.aligned.m16n8k16.row.col.f32.f16.f16.f32 "
        "{%0,%1,%2,%3}, {%4,%5,%6,%7}, {%8,%9}, {%0,%1,%2,%3};"
        : "+f"(d[0]), "+f"(d[1]), "+f"(d[2]), "+f"(d[3])
        : "r"(a[0]), "r"(a[1]), "r"(a[2]), "r"(a[3]), "r"(b[0]), "r"(b[1]));
}

__device__ __forceinline__ void split2h(float v, __half& h, __half& l) {
    h = __float2half_rn(v);
    l = __float2half_rn(v - __half2float(h));
}

// ---------------- GEMM tiling ----------------
#define BM 64
#define BN 64
#define BK 32
#define NCHUNK (GD / BK)              // 8
#define LDT 40                        // padded row stride (fp16 elems)
#define TILE_T (64 * LDT * 2)         // 5120 B per 64x32 fp16 tile
#define OFF_AH 0
#define OFF_AL TILE_T
#define OFF_W  (2 * TILE_T)
#define STAGE_B (3 * TILE_T)          // 15360
#define NSTAGE 3
#define SMEM_TOTAL (NSTAGE * STAGE_B) // 46080

// fragment bundle for one k16 slice (per warp)
struct Frag {
    uint32_t ah[2][4], al[2][4];
    uint32_t w[2][4];
};

// C[8192,256] = A @ W^T + bias; A as fp16 (hi,lo), W single fp16.
// grid (128, 4); 128 thr = 4 warps in 2(m) x 2(n); warp tile 32x32.
template <bool RELU, bool WSPLIT, bool WF32, bool F32_COND>
__global__ void __launch_bounds__(128, 4)
gemm_mma(const __half* __restrict__ Ah, const __half* __restrict__ Al,
         const __half* __restrict__ W,
         const float* __restrict__ bias, const float* __restrict__ eps,
         __half* __restrict__ Oh, __half* __restrict__ Ol,
         float* __restrict__ Of) {
    extern __shared__ __align__(16) char smem[];
    const uint32_t sb = smem_u32(smem);
    const int tid = threadIdx.x;
    const int wid = tid >> 5;
    const int lane = tid & 31;
    const int warp_m = wid & 1;
    const int warp_n = wid >> 1;
    const int bm = blockIdx.x * BM;
    const int bn = blockIdx.y * BN;

    float acc[2][4][4];
#pragma unroll
    for (int i = 0; i < 2; i++)
#pragma unroll
        for (int j = 0; j < 4; j++)
#pragma unroll
            for (int k = 0; k < 4; k++) acc[i][j][k] = 0.0f;

    const uint32_t a_off_base =
        (uint32_t)((warp_m * 32 + (lane & 15)) * LDT + (lane >> 4) * 8) * 2;
    const int mmat = lane >> 3;
    const uint32_t w_off_base =
        (uint32_t)((warp_n * 32 + (lane & 7) + ((mmat >> 1) & 1) * 8) * LDT +
                   (mmat & 1) * 8) * 2;

    auto ld_frag = [&](Frag& f, uint32_t stage_base, int k16) {
        const uint32_t kadd = (uint32_t)(k16 * 16) * 2;
#pragma unroll
        for (int mi = 0; mi < 2; mi++) {
            const uint32_t off = a_off_base + kadd + (uint32_t)(mi * 16 * LDT) * 2;
            ldsm_x4(f.ah[mi], stage_base + OFF_AH + off);
            ldsm_x4(f.al[mi], stage_base + OFF_AL + off);
        }
#pragma unroll
        for (int ni = 0; ni < 2; ni++) {
            const uint32_t off = w_off_base + kadd + (uint32_t)(ni * 16 * LDT) * 2;
            ldsm_x4(f.w[ni], stage_base + OFF_W + off);
        }
    };

    auto do_mma = [&](const Frag& f) {
#pragma unroll
        for (int mi = 0; mi < 2; mi++)
#pragma unroll
            for (int n8 = 0; n8 < 4; n8++)
                mma16816(acc[mi][n8], f.ah[mi], &f.w[n8 >> 1][(n8 & 1) * 2]);
#pragma unroll
        for (int mi = 0; mi < 2; mi++)
#pragma unroll
            for (int n8 = 0; n8 < 4; n8++)
                mma16816(acc[mi][n8], f.al[mi], &f.w[n8 >> 1][(n8 & 1) * 2]);
    };

    auto load_stage = [&](int s, int kc) {
        const uint32_t base = sb + s * STAGE_B;
        const int k0 = kc * BK;
#pragma unroll
        for (int it = 0; it < 2; it++) {
            const int j = tid + it * 128;
            const int row = j >> 2;
            const int q = j & 3;
            const uint32_t soff = (uint32_t)(row * LDT + q * 8) * 2;
            const size_t ga = (size_t)(bm + row) * GD + k0 + q * 8;
            const size_t gw = (size_t)(bn + row) * GD + k0 + q * 8;
            cp_async16(base + OFF_AH + soff, Ah + ga);
            cp_async16(base + OFF_AL + soff, Al + ga);
            cp_async16(base + OFF_W + soff, W + gw);
        }
    };

    load_stage(0, 0);
    CP_COMMIT();
    load_stage(1, 1);
    CP_COMMIT();
    CP_WAIT(1);
    __syncthreads();

    Frag cur, nxt;
    ld_frag(cur, sb + 0 * STAGE_B, 0);

    int stage = 0;
    for (int kc = 0; kc < NCHUNK; kc++) {
        const uint32_t base = sb + stage * STAGE_B;
        ld_frag(nxt, base, 1);
        do_mma(cur);

        if (kc < NCHUNK - 2) {
            load_stage((stage + 2) % NSTAGE, kc + 2);
            CP_COMMIT();
        }
        if (kc < NCHUNK - 1) {
            if (kc < NCHUNK - 2) { CP_WAIT(1); } else { CP_WAIT(0); }
            __syncthreads();
        }

        do_mma(nxt);
        if (kc < NCHUNK - 1) {
            stage = (stage + 1) % NSTAGE;
            ld_frag(cur, sb + stage * STAGE_B, 0);
        }
    }

    // ---- epilogue
    const bool do_f32 = WF32 && (!F32_COND || __ldg(eps) != 0.0f);
    const int r = lane >> 2;
    const int c2 = (lane & 3) * 2;
#pragma unroll
    for (int mi = 0; mi < 2; mi++) {
#pragma unroll
        for (int half = 0; half < 2; half++) {
            const int m = bm + warp_m * 32 + mi * 16 + r + half * 8;
#pragma unroll
            for (int n8 = 0; n8 < 4; n8++) {
                const int n = bn + warp_n * 32 + n8 * 8 + c2;
                float v0 = acc[mi][n8][half * 2 + 0] + __ldg(bias + n);
                float v1 = acc[mi][n8][half * 2 + 1] + __ldg(bias + n + 1);
                if (RELU) { v0 = fmaxf(v0, 0.0f); v1 = fmaxf(v1, 0.0f); }
                if (WF32) {
                    if (do_f32)
                        *(float2*)(Of + (size_t)m * GD + n) = make_float2(v0, v1);
                }
                if (WSPLIT) {
                    __half h0, l0, h1, l1;
                    split2h(v0, h0, l0);
                    split2h(v1, h1, l1);
                    __half2 hp, lp;
                    hp.x = h0; hp.y = h1;
                    lp.x = l0; lp.y = l1;
                    *(__half2*)(Oh + (size_t)m * GD + n) = hp;
                    *(__half2*)(Ol + (size_t)m * GD + n) = lp;
                }
            }
        }
    }
}

// ---------------------------------------------------------------------------
// Weight convert: W1,W2 fp32 -> fp16
// ---------------------------------------------------------------------------
__global__ void __launch_bounds__(256) wconv_kernel(
    const float* __restrict__ W1, const float* __restrict__ W2,
    __half* __restrict__ W1h, __half* __restrict__ W2h) {
    const int i = blockIdx.x * 256 + threadIdx.x;
    W1h[i] = __float2half_rn(W1[i]);
    W2h[i] = __float2half_rn(W2[i]);
}

// ---------------------------------------------------------------------------
// Input aggregation + split:  y = x + eps*(adj@x); write fp16 split(y).
// ---------------------------------------------------------------------------
__global__ void __launch_bounds__(256) split_agg_kernel(
    const float* __restrict__ x, const float* __restrict__ adj,
    const float* __restrict__ eps,
    __half* __restrict__ oh, __half* __restrict__ ol) {
    const float e = eps[0];
    const int i0 = blockIdx.x * blockDim.x + threadIdx.x;
    const int stride = gridDim.x * blockDim.x;
    if (e == 0.0f) {
        const float4* x4 = (const float4*)x;
        for (int i = i0; i < GN * GD / 8; i += stride) {
            float4 a = x4[2 * i];
            float4 b = x4[2 * i + 1];
            __half h[8], l[8];
            split2h(a.x, h[0], l[0]); split2h(a.y, h[1], l[1]);
            split2h(a.z, h[2], l[2]); split2h(a.w, h[3], l[3]);
            split2h(b.x, h[4], l[4]); split2h(b.y, h[5], l[5]);
            split2h(b.z, h[6], l[6]); split2h(b.w, h[7], l[7]);
            *(uint4*)(oh + (size_t)i * 8) = *(uint4*)h;
            *(uint4*)(ol + (size_t)i * 8) = *(uint4*)l;
        }
    } else {
        for (int i = i0; i < GN * GD; i += stride) {
            const int row = i >> 8, col = i & 255;
            float s = 0.0f;
            const float* arow = adj + (size_t)row * GN;
            for (int k = 0; k < GN; k++) s += arow[k] * x[(size_t)k * GD + col];
            __half h, l;
            split2h(x[i] + e * s, h, l);
            oh[i] = h; ol[i] = l;
        }
    }
}

// Between-layer fixup: if eps != 0, recompute split(x + eps*adj@x) from fp32.
__global__ void __launch_bounds__(256) agg_fix_kernel(
    const float* __restrict__ xin, const float* __restrict__ adj,
    const float* __restrict__ eps,
    __half* __restrict__ oh, __half* __restrict__ ol) {
    const float e = eps[0];
    if (e == 0.0f) return;
    const int i0 = blockIdx.x * blockDim.x + threadIdx.x;
    const int stride = gridDim.x * blockDim.x;
    for (int i = i0; i < GN * GD; i += stride) {
        const int row = i >> 8, col = i & 255;
        float s = 0.0f;
        const float* arow = adj + (size_t)row * GN;
        for (int k = 0; k < GN; k++) s += arow[k] * xin[(size_t)k * GD + col];
        __half h, l;
        split2h(xin[i] + e * s, h, l);
        oh[i] = h; ol[i] = l;
    }
}

// ---------------------------------------------------------------------------
// kernel_launch
// ---------------------------------------------------------------------------
extern "C" void kernel_launch(void* const* d_in, const int* in_sizes, int n_in,
                              void* d_out, int out_size) {
    const float* x   = (const float*)d_in[0];
    const float* adj = (const float*)d_in[1];
    const float* W1  = (const float*)d_in[2];
    const float* b1  = (const float*)d_in[3];
    const float* W2  = (const float*)d_in[4];
    const float* b2  = (const float*)d_in[5];
    const float* eps = (const float*)d_in[6];
    float* out = (float*)d_out;

    __half *Ah, *Al, *Bh, *Bl, *W1h, *W2h;
    float* F;
    cudaGetSymbolAddress((void**)&Ah, g_Ah);
    cudaGetSymbolAddress((void**)&Al, g_Al);
    cudaGetSymbolAddress((void**)&Bh, g_Bh);
    cudaGetSymbolAddress((void**)&Bl, g_Bl);
    cudaGetSymbolAddress((void**)&W1h, g_W1);
    cudaGetSymbolAddress((void**)&W2h, g_W2);
    cudaGetSymbolAddress((void**)&F, g_F);

    // max dynamic smem + full carveout so 4 CTAs/SM fit (4 x 46080 = 184KB)
    cudaFuncSetAttribute(gemm_mma<true, true, false, false>,
                         cudaFuncAttributeMaxDynamicSharedMemorySize, SMEM_TOTAL);
    cudaFuncSetAttribute(gemm_mma<false, true, true, true>,
                         cudaFuncAttributeMaxDynamicSharedMemorySize, SMEM_TOTAL);
    cudaFuncSetAttribute(gemm_mma<false, false, true, false>,
                         cudaFuncAttributeMaxDynamicSharedMemorySize, SMEM_TOTAL);
    cudaFuncSetAttribute(gemm_mma<true, true, false, false>,
                         cudaFuncAttributePreferredSharedMemoryCarveout, 100);
    cudaFuncSetAttribute(gemm_mma<false, true, true, true>,
                         cudaFuncAttributePreferredSharedMemoryCarveout, 100);
    cudaFuncSetAttribute(gemm_mma<false, false, true, false>,
                         cudaFuncAttributePreferredSharedMemoryCarveout, 100);

    const dim3 ggrid(GN / BM, GD / BN);   // (128, 4) = 512 CTAs

    // prep
    wconv_kernel<<<256, 256>>>(W1, W2, W1h, W2h);
    split_agg_kernel<<<1184, 256>>>(x, adj, eps, Ah, Al);

    // layer 1
    gemm_mma<true, true, false, false><<<ggrid, 128, SMEM_TOTAL>>>(
        Ah, Al, W1h, b1, eps, Bh, Bl, nullptr);
    gemm_mma<false, true, true, true><<<ggrid, 128, SMEM_TOTAL>>>(
        Bh, Bl, W2h, b2, eps, Ah, Al, F);

    // layer 2
    agg_fix_kernel<<<512, 256>>>(F, adj, eps, Ah, Al);
    gemm_mma<true, true, false, false><<<ggrid, 128, SMEM_TOTAL>>>(
        Ah, Al, W1h, b1, eps, Bh, Bl, nullptr);
    gemm_mma<false, false, true, false><<<ggrid, 128, SMEM_TOTAL>>>(
        Bh, Bl, W2h, b2, eps, nullptr, nullptr, out);
}

// round 14
// speedup vs baseline: 1.5253x; 1.5253x over previous
#include <cuda_runtime.h>
#include <cuda_fp16.h>
#include <cstdint>

// GIN (N=8192, D=256), 2 layers. R14: fully smem-resident GEMM — per-CTA
// 128x64 tile keeps the ENTIRE A strip (128x256) and W strip (64x256) in
// shared memory: one bulk cp.async load, ONE __syncthreads, then 16 k-steps
// of barrier-free ldsm+MMA. Single-pass fp16 (A fp16, W fp16, fp32 accum).

#define GN 8192
#define GD 256

// ---------------- scratch (__device__ globals; no allocation allowed) ----------------
__device__ __half g_A[GN * GD];
__device__ __half g_B[GN * GD];
__device__ __half g_W1[GD * GD];
__device__ __half g_W2[GD * GD];
__device__ float g_F[GN * GD];

// ---------------- PTX helpers (sm_80-era, compute_103-legal) ----------------
__device__ __forceinline__ uint32_t smem_u32(const void* p) {
    uint32_t a;
    asm("{ .reg .u64 t; cvta.to.shared.u64 t, %1; cvt.u32.u64 %0, t; }"
        : "=r"(a) : "l"(p));
    return a;
}

__device__ __forceinline__ void cp_async16(uint32_t s, const void* g) {
    asm volatile("cp.async.cg.shared.global [%0], [%1], 16;" :: "r"(s), "l"(g));
}
#define CP_COMMIT() asm volatile("cp.async.commit_group;" ::: "memory")
#define CP_WAIT(n)  asm volatile("cp.async.wait_group %0;" :: "n"(n) : "memory")

__device__ __forceinline__ void ldsm_x4(uint32_t* r, uint32_t addr) {
    asm volatile("ldmatrix.sync.aligned.m8n8.x4.shared.b16 {%0,%1,%2,%3}, [%4];"
                 : "=r"(r[0]), "=r"(r[1]), "=r"(r[2]), "=r"(r[3]) : "r"(addr));
}

__device__ __forceinline__ void mma16816(float* d, const uint32_t* a,
                                         const uint32_t* b) {
    asm volatile(
        "mma.sync.aligned.m16n8k16.row.col.f32.f16.f16.f32 "
        "{%0,%1,%2,%3}, {%4,%5,%6,%7}, {%8,%9}, {%0,%1,%2,%3};"
        : "+f"(d[0]), "+f"(d[1]), "+f"(d[2]), "+f"(d[3])
        : "r"(a[0]), "r"(a[1]), "r"(a[2]), "r"(a[3]), "r"(b[0]), "r"(b[1]));
}

// ---------------- GEMM tiling ----------------
#define BM 128
#define BN 64
#define NK16 (GD / 16)                // 16 k-steps
#define LDT 264                       // padded row stride (fp16): 256 + 8
#define A_BYTES (BM * LDT * 2)        // 67584
#define W_BYTES (BN * LDT * 2)        // 33792
#define OFF_A 0
#define OFF_W A_BYTES
#define SMEM_TOTAL (A_BYTES + W_BYTES)  // 101376

struct Frag {
    uint32_t a[2][4];   // two m16 tiles
    uint32_t w[2][4];   // two n16 tiles
};

// C[8192,256] = A @ W^T + bias; fp16 inputs, fp32 accum.
// grid (64, 4); 256 thr = 8 warps in 4(m) x 2(n); warp tile 32x32.
template <bool RELU, bool WH16, bool WF32, bool F32_COND>
__global__ void __launch_bounds__(256, 2)
gemm_res(const __half* __restrict__ A, const __half* __restrict__ W,
         const float* __restrict__ bias, const float* __restrict__ eps,
         __half* __restrict__ Oh, float* __restrict__ Of) {
    extern __shared__ __align__(16) char smem[];
    const uint32_t sb = smem_u32(smem);
    const int tid = threadIdx.x;
    const int wid = tid >> 5;
    const int lane = tid & 31;
    const int warp_m = wid & 3;       // 4 warps along M
    const int warp_n = wid >> 2;      // 2 warps along N
    const int bm = blockIdx.x * BM;
    const int bn = blockIdx.y * BN;

    // ---- bulk load: whole A strip (128x256) + W strip (64x256)
    {
        // A: 128 rows x 512B = 4096 16B-chunks; 16 per thread
#pragma unroll
        for (int it = 0; it < 16; it++) {
            const int idx = tid + it * 256;       // 0..4095
            const int row = idx >> 5;
            const int q = idx & 31;
            cp_async16(sb + OFF_A + (uint32_t)(row * LDT * 2 + q * 16),
                       A + (size_t)(bm + row) * GD + q * 8);
        }
        // W: 64 rows x 512B = 2048 chunks; 8 per thread
#pragma unroll
        for (int it = 0; it < 8; it++) {
            const int idx = tid + it * 256;       // 0..2047
            const int row = idx >> 5;
            const int q = idx & 31;
            cp_async16(sb + OFF_W + (uint32_t)(row * LDT * 2 + q * 16),
                       W + (size_t)(bn + row) * GD + q * 8);
        }
    }
    CP_COMMIT();

    float acc[2][4][4];
#pragma unroll
    for (int i = 0; i < 2; i++)
#pragma unroll
        for (int j = 0; j < 4; j++)
#pragma unroll
            for (int k = 0; k < 4; k++) acc[i][j][k] = 0.0f;

    const uint32_t a_base = sb + OFF_A +
        (uint32_t)((warp_m * 32 + (lane & 15)) * LDT + (lane >> 4) * 8) * 2;
    const int mmat = lane >> 3;
    const uint32_t w_base = sb + OFF_W +
        (uint32_t)((warp_n * 32 + (lane & 7) + ((mmat >> 1) & 1) * 8) * LDT +
                   (mmat & 1) * 8) * 2;

    CP_WAIT(0);
    __syncthreads();    // the ONLY barrier before the epilogue

    Frag fr[2];
    // prime k16 = 0
#pragma unroll
    for (int mi = 0; mi < 2; mi++)
        ldsm_x4(fr[0].a[mi], a_base + (uint32_t)(mi * 16 * LDT) * 2);
#pragma unroll
    for (int ni = 0; ni < 2; ni++)
        ldsm_x4(fr[0].w[ni], w_base + (uint32_t)(ni * 16 * LDT) * 2);

#pragma unroll
    for (int k16 = 0; k16 < NK16; k16++) {
        const int cb = k16 & 1;
        if (k16 < NK16 - 1) {
            const uint32_t kadd = (uint32_t)((k16 + 1) * 16) * 2;
#pragma unroll
            for (int mi = 0; mi < 2; mi++)
                ldsm_x4(fr[cb ^ 1].a[mi],
                        a_base + kadd + (uint32_t)(mi * 16 * LDT) * 2);
#pragma unroll
            for (int ni = 0; ni < 2; ni++)
                ldsm_x4(fr[cb ^ 1].w[ni],
                        w_base + kadd + (uint32_t)(ni * 16 * LDT) * 2);
        }
#pragma unroll
        for (int mi = 0; mi < 2; mi++)
#pragma unroll
            for (int n8 = 0; n8 < 4; n8++)
                mma16816(acc[mi][n8], fr[cb].a[mi],
                         &fr[cb].w[n8 >> 1][(n8 & 1) * 2]);
    }

    // ---- epilogue
    const bool do_f32 = WF32 && (!F32_COND || __ldg(eps) != 0.0f);
    const int r = lane >> 2;
    const int c2 = (lane & 3) * 2;
#pragma unroll
    for (int mi = 0; mi < 2; mi++) {
#pragma unroll
        for (int half = 0; half < 2; half++) {
            const int m = bm + warp_m * 32 + mi * 16 + r + half * 8;
#pragma unroll
            for (int n8 = 0; n8 < 4; n8++) {
                const int n = bn + warp_n * 32 + n8 * 8 + c2;
                float v0 = acc[mi][n8][half * 2 + 0] + __ldg(bias + n);
                float v1 = acc[mi][n8][half * 2 + 1] + __ldg(bias + n + 1);
                if (RELU) { v0 = fmaxf(v0, 0.0f); v1 = fmaxf(v1, 0.0f); }
                if (WF32) {
                    if (do_f32)
                        *(float2*)(Of + (size_t)m * GD + n) = make_float2(v0, v1);
                }
                if (WH16) {
                    __half2 hp;
                    hp.x = __float2half_rn(v0);
                    hp.y = __float2half_rn(v1);
                    *(__half2*)(Oh + (size_t)m * GD + n) = hp;
                }
            }
        }
    }
}

// ---------------------------------------------------------------------------
// Weight convert: W1,W2 fp32 -> fp16
// ---------------------------------------------------------------------------
__global__ void __launch_bounds__(256) wconv_kernel(
    const float* __restrict__ W1, const float* __restrict__ W2,
    __half* __restrict__ W1h, __half* __restrict__ W2h) {
    const int i = blockIdx.x * 256 + threadIdx.x;
    W1h[i] = __float2half_rn(W1[i]);
    W2h[i] = __float2half_rn(W2[i]);
}

// ---------------------------------------------------------------------------
// Input: y = x + eps*(adj@x) -> fp16. eps==0 fast path: y = x.
// ---------------------------------------------------------------------------
__global__ void __launch_bounds__(256) conv_agg_kernel(
    const float* __restrict__ x, const float* __restrict__ adj,
    const float* __restrict__ eps, __half* __restrict__ o) {
    const float e = eps[0];
    const int i0 = blockIdx.x * blockDim.x + threadIdx.x;
    const int stride = gridDim.x * blockDim.x;
    if (e == 0.0f) {
        const float4* x4 = (const float4*)x;
        for (int i = i0; i < GN * GD / 8; i += stride) {
            float4 a = x4[2 * i];
            float4 b = x4[2 * i + 1];
            __half h[8];
            h[0] = __float2half_rn(a.x); h[1] = __float2half_rn(a.y);
            h[2] = __float2half_rn(a.z); h[3] = __float2half_rn(a.w);
            h[4] = __float2half_rn(b.x); h[5] = __float2half_rn(b.y);
            h[6] = __float2half_rn(b.z); h[7] = __float2half_rn(b.w);
            *(uint4*)(o + (size_t)i * 8) = *(uint4*)h;
        }
    } else {
        for (int i = i0; i < GN * GD; i += stride) {
            const int row = i >> 8, col = i & 255;
            float s = 0.0f;
            const float* arow = adj + (size_t)row * GN;
            for (int k = 0; k < GN; k++) s += arow[k] * x[(size_t)k * GD + col];
            o[i] = __float2half_rn(x[i] + e * s);
        }
    }
}

// Between-layer fixup: if eps != 0, recompute fp16(x + eps*adj@x) from fp32.
__global__ void __launch_bounds__(256) agg_fix_kernel(
    const float* __restrict__ xin, const float* __restrict__ adj,
    const float* __restrict__ eps, __half* __restrict__ o) {
    const float e = eps[0];
    if (e == 0.0f) return;
    const int i0 = blockIdx.x * blockDim.x + threadIdx.x;
    const int stride = gridDim.x * blockDim.x;
    for (int i = i0; i < GN * GD; i += stride) {
        const int row = i >> 8, col = i & 255;
        float s = 0.0f;
        const float* arow = adj + (size_t)row * GN;
        for (int k = 0; k < GN; k++) s += arow[k] * xin[(size_t)k * GD + col];
        o[i] = __float2half_rn(xin[i] + e * s);
    }
}

// ---------------------------------------------------------------------------
// kernel_launch
// ---------------------------------------------------------------------------
extern "C" void kernel_launch(void* const* d_in, const int* in_sizes, int n_in,
                              void* d_out, int out_size) {
    const float* x   = (const float*)d_in[0];
    const float* adj = (const float*)d_in[1];
    const float* W1  = (const float*)d_in[2];
    const float* b1  = (const float*)d_in[3];
    const float* W2  = (const float*)d_in[4];
    const float* b2  = (const float*)d_in[5];
    const float* eps = (const float*)d_in[6];
    float* out = (float*)d_out;

    __half *A, *B, *W1h, *W2h;
    float* F;
    cudaGetSymbolAddress((void**)&A, g_A);
    cudaGetSymbolAddress((void**)&B, g_B);
    cudaGetSymbolAddress((void**)&W1h, g_W1);
    cudaGetSymbolAddress((void**)&W2h, g_W2);
    cudaGetSymbolAddress((void**)&F, g_F);

    cudaFuncSetAttribute(gemm_res<true, true, false, false>,
                         cudaFuncAttributeMaxDynamicSharedMemorySize, SMEM_TOTAL);
    cudaFuncSetAttribute(gemm_res<false, true, true, true>,
                         cudaFuncAttributeMaxDynamicSharedMemorySize, SMEM_TOTAL);
    cudaFuncSetAttribute(gemm_res<false, false, true, false>,
                         cudaFuncAttributeMaxDynamicSharedMemorySize, SMEM_TOTAL);

    const dim3 ggrid(GN / BM, GD / BN);   // (64, 4) = 256 CTAs, 1 wave @ 2/SM

    // prep
    wconv_kernel<<<256, 256>>>(W1, W2, W1h, W2h);
    conv_agg_kernel<<<1184, 256>>>(x, adj, eps, A);

    // layer 1
    gemm_res<true, true, false, false><<<ggrid, 256, SMEM_TOTAL>>>(
        A, W1h, b1, eps, B, nullptr);
    gemm_res<false, true, true, true><<<ggrid, 256, SMEM_TOTAL>>>(
        B, W2h, b2, eps, A, F);

    // layer 2
    agg_fix_kernel<<<512, 256>>>(F, adj, eps, A);
    gemm_res<true, true, false, false><<<ggrid, 256, SMEM_TOTAL>>>(
        A, W1h, b1, eps, B, nullptr);
    gemm_res<false, false, true, false><<<ggrid, 256, SMEM_TOTAL>>>(
        B, W2h, b2, eps, nullptr, out);
}

// round 15
// speedup vs baseline: 1.7132x; 1.1232x over previous
#include <cuda_runtime.h>
#include <cuda_fp16.h>
#include <cstdint>

// GIN (N=8192, D=256), 2 layers. R15: fused per-layer MLP kernel.
// One CTA = 64 M-rows, 1 CTA/SM, 203KB smem: A(64x256) | W(256x256) | H(64x256).
// Phase1: H = relu(A@W1^T + b1) kept in smem. W slot reloaded with W2 (k-split
// cp.async). Phase2: out = H@W2^T + b2. Single-pass fp16 HMMA, fp32 accum.

#define GN 8192
#define GD 256

// ---------------- scratch (__device__ globals; no allocation allowed) ----------------
__device__ __half g_A[GN * GD];
__device__ __half g_B[GN * GD];
__device__ __half g_W1[GD * GD];
__device__ __half g_W2[GD * GD];
__device__ float g_F[GN * GD];

// ---------------- PTX helpers (sm_80-era, compute_103-legal) ----------------
__device__ __forceinline__ uint32_t smem_u32(const void* p) {
    uint32_t a;
    asm("{ .reg .u64 t; cvta.to.shared.u64 t, %1; cvt.u32.u64 %0, t; }"
        : "=r"(a) : "l"(p));
    return a;
}

__device__ __forceinline__ void cp_async16(uint32_t s, const void* g) {
    asm volatile("cp.async.cg.shared.global [%0], [%1], 16;" :: "r"(s), "l"(g));
}
#define CP_COMMIT() asm volatile("cp.async.commit_group;" ::: "memory")
#define CP_WAIT(n)  asm volatile("cp.async.wait_group %0;" :: "n"(n) : "memory")

__device__ __forceinline__ void ldsm_x4(uint32_t* r, uint32_t addr) {
    asm volatile("ldmatrix.sync.aligned.m8n8.x4.shared.b16 {%0,%1,%2,%3}, [%4];"
                 : "=r"(r[0]), "=r"(r[1]), "=r"(r[2]), "=r"(r[3]) : "r"(addr));
}

__device__ __forceinline__ void mma16816(float* d, const uint32_t* a,
                                         const uint32_t* b) {
    asm volatile(
        "mma.sync.aligned.m16n8k16.row.col.f32.f16.f16.f32 "
        "{%0,%1,%2,%3}, {%4,%5,%6,%7}, {%8,%9}, {%0,%1,%2,%3};"
        : "+f"(d[0]), "+f"(d[1]), "+f"(d[2]), "+f"(d[3])
        : "r"(a[0]), "r"(a[1]), "r"(a[2]), "r"(a[3]), "r"(b[0]), "r"(b[1]));
}

// ---------------- tiling ----------------
#define BM 64
#define LDT 264                          // padded row stride (fp16)
#define LDTB (LDT * 2)                   // 528 bytes
#define A_BYTES (BM * LDTB)              // 33792
#define W_BYTES (GD * LDTB)              // 135168
#define OFF_A 0
#define OFF_W A_BYTES
#define OFF_H (A_BYTES + W_BYTES)        // 168960
#define SMEM_TOTAL (OFF_H + A_BYTES)     // 202752

struct FragP {
    uint32_t a[2][4];    // two m16 tiles
    uint32_t w[4][4];    // four n16 tiles (warp covers 64 N-cols)
};

// Fused layer: out = (relu(In@W1^T + b1))@W2^T + b2, In/W fp16, fp32 accum.
// grid 128; 256 thr = 8 warps in 2(m) x 4(n); warp tile 32x64.
// LAST=false: write fp16 Oh (+ fp32 Of when eps!=0). LAST=true: write fp32 Of.
template <bool LAST>
__global__ void __launch_bounds__(256, 1)
mlp_layer(const __half* __restrict__ in0, const __half* __restrict__ in1,
          const __half* __restrict__ W1, const __half* __restrict__ W2,
          const float* __restrict__ b1, const float* __restrict__ b2,
          const float* __restrict__ eps,
          __half* __restrict__ Oh, float* __restrict__ Of) {
    extern __shared__ __align__(16) char smem[];
    const uint32_t sb = smem_u32(smem);
    const int tid = threadIdx.x;
    const int wid = tid >> 5;
    const int lane = tid & 31;
    const int warp_m = wid & 1;          // 2 warps along M (32 rows)
    const int warp_n = wid >> 1;         // 4 warps along N (64 cols)
    const int bm = blockIdx.x * BM;

    const float e = __ldg(eps);
    const __half* In = (e == 0.0f) ? in0 : in1;

    // ---- loaders (k-half granularity) ----
    auto load_A_half = [&](int g) {                  // 64 rows x 128 cols
#pragma unroll
        for (int it = 0; it < 4; it++) {
            const int idx = tid + it * 256;          // 0..1023
            const int row = idx >> 4;
            const int q = idx & 15;
            cp_async16(sb + OFF_A + (uint32_t)(row * LDTB + g * 256 + q * 16),
                       In + (size_t)(bm + row) * GD + g * 128 + q * 8);
        }
    };
    auto load_W_half = [&](const __half* W, int g) { // 256 rows x 128 cols
#pragma unroll
        for (int it = 0; it < 16; it++) {
            const int idx = tid + it * 256;          // 0..4095
            const int row = idx >> 4;
            const int q = idx & 15;
            cp_async16(sb + OFF_W + (uint32_t)(row * LDTB + g * 256 + q * 16),
                       W + (size_t)row * GD + g * 128 + q * 8);
        }
    };

    // ---- fragment addressing ----
    const uint32_t a_rel =
        (uint32_t)((warp_m * 32 + (lane & 15)) * LDTB) + (uint32_t)(lane >> 4) * 16;
    const int mmat = lane >> 3;
    const uint32_t w_rel =
        (uint32_t)((warp_n * 64 + (lane & 7) + ((mmat >> 1) & 1) * 8) * LDTB) +
        (uint32_t)(mmat & 1) * 16;

    float acc[2][8][4];

    auto ld_frags = [&](FragP& f, uint32_t abase, uint32_t wbase, int k16) {
        const uint32_t kadd = (uint32_t)k16 * 32;
#pragma unroll
        for (int mi = 0; mi < 2; mi++)
            ldsm_x4(f.a[mi], abase + a_rel + kadd + (uint32_t)(mi * 16 * LDTB));
#pragma unroll
        for (int ni = 0; ni < 4; ni++)
            ldsm_x4(f.w[ni], wbase + w_rel + kadd + (uint32_t)(ni * 16 * LDTB));
    };

    // 8 k16-steps with register double-buffered fragments (no barriers inside)
    auto run8 = [&](uint32_t abase, uint32_t wbase, int k0) {
        FragP fr[2];
        ld_frags(fr[0], abase, wbase, k0);
#pragma unroll
        for (int i = 0; i < 8; i++) {
            const int cb = i & 1;
            if (i < 7) ld_frags(fr[cb ^ 1], abase, wbase, k0 + i + 1);
#pragma unroll
            for (int mi = 0; mi < 2; mi++)
#pragma unroll
                for (int n8 = 0; n8 < 8; n8++)
                    mma16816(acc[mi][n8], fr[cb].a[mi],
                             &fr[cb].w[n8 >> 1][(n8 & 1) * 2]);
        }
    };

#pragma unroll
    for (int i = 0; i < 2; i++)
#pragma unroll
        for (int j = 0; j < 8; j++)
#pragma unroll
            for (int k = 0; k < 4; k++) acc[i][j][k] = 0.0f;

    // ================= phase 1: H = relu(A @ W1^T + b1) =================
    load_A_half(0); load_W_half(W1, 0); CP_COMMIT();
    load_A_half(1); load_W_half(W1, 1); CP_COMMIT();
    CP_WAIT(1);
    __syncthreads();
    run8(sb + OFF_A, sb + OFF_W, 0);
    CP_WAIT(0);
    __syncthreads();
    run8(sb + OFF_A, sb + OFF_W, 8);
    __syncthreads();                 // all warps done reading W1 / A

    // start W2 load into the W slot (overwrites W1)
    load_W_half(W2, 0); CP_COMMIT();
    load_W_half(W2, 1); CP_COMMIT();

    // store H (bias + relu + fp16) into smem H slot
    const int r = lane >> 2;
    const int c2 = (lane & 3) * 2;
#pragma unroll
    for (int mi = 0; mi < 2; mi++) {
#pragma unroll
        for (int half = 0; half < 2; half++) {
            const int rowl = warp_m * 32 + mi * 16 + r + half * 8;
#pragma unroll
            for (int n8 = 0; n8 < 8; n8++) {
                const int n = warp_n * 64 + n8 * 8 + c2;
                float v0 = acc[mi][n8][half * 2 + 0] + __ldg(b1 + n);
                float v1 = acc[mi][n8][half * 2 + 1] + __ldg(b1 + n + 1);
                v0 = fmaxf(v0, 0.0f);
                v1 = fmaxf(v1, 0.0f);
                __half2 hp;
                hp.x = __float2half_rn(v0);
                hp.y = __float2half_rn(v1);
                *(__half2*)(smem + OFF_H + rowl * LDTB + n * 2) = hp;
            }
        }
    }

    // reset accumulators
#pragma unroll
    for (int i = 0; i < 2; i++)
#pragma unroll
        for (int j = 0; j < 8; j++)
#pragma unroll
            for (int k = 0; k < 4; k++) acc[i][j][k] = 0.0f;

    // ================= phase 2: out = H @ W2^T + b2 =================
    CP_WAIT(1);                      // W2 lower k-half in
    __syncthreads();                 // + H stores visible
    run8(sb + OFF_H, sb + OFF_W, 0);
    CP_WAIT(0);
    __syncthreads();
    run8(sb + OFF_H, sb + OFF_W, 8);

    // ---- epilogue ----
    const bool do_f32 = (!LAST) && (e != 0.0f);
#pragma unroll
    for (int mi = 0; mi < 2; mi++) {
#pragma unroll
        for (int half = 0; half < 2; half++) {
            const int m = bm + warp_m * 32 + mi * 16 + r + half * 8;
#pragma unroll
            for (int n8 = 0; n8 < 8; n8++) {
                const int n = warp_n * 64 + n8 * 8 + c2;
                float v0 = acc[mi][n8][half * 2 + 0] + __ldg(b2 + n);
                float v1 = acc[mi][n8][half * 2 + 1] + __ldg(b2 + n + 1);
                if (LAST) {
                    *(float2*)(Of + (size_t)m * GD + n) = make_float2(v0, v1);
                } else {
                    __half2 hp;
                    hp.x = __float2half_rn(v0);
                    hp.y = __float2half_rn(v1);
                    *(__half2*)(Oh + (size_t)m * GD + n) = hp;
                    if (do_f32)
                        *(float2*)(Of + (size_t)m * GD + n) = make_float2(v0, v1);
                }
            }
        }
    }
}

// ---------------------------------------------------------------------------
// Weight convert: W1,W2 fp32 -> fp16
// ---------------------------------------------------------------------------
__global__ void __launch_bounds__(256) wconv_kernel(
    const float* __restrict__ W1, const float* __restrict__ W2,
    __half* __restrict__ W1h, __half* __restrict__ W2h) {
    const int i = blockIdx.x * 256 + threadIdx.x;
    W1h[i] = __float2half_rn(W1[i]);
    W2h[i] = __float2half_rn(W2[i]);
}

// ---------------------------------------------------------------------------
// Input: y = x + eps*(adj@x) -> fp16. eps==0 fast path: y = x.
// ---------------------------------------------------------------------------
__global__ void __launch_bounds__(256) conv_agg_kernel(
    const float* __restrict__ x, const float* __restrict__ adj,
    const float* __restrict__ eps, __half* __restrict__ o) {
    const float e = eps[0];
    const int i0 = blockIdx.x * blockDim.x + threadIdx.x;
    const int stride = gridDim.x * blockDim.x;
    if (e == 0.0f) {
        const float4* x4 = (const float4*)x;
        for (int i = i0; i < GN * GD / 8; i += stride) {
            float4 a = x4[2 * i];
            float4 b = x4[2 * i + 1];
            __half h[8];
            h[0] = __float2half_rn(a.x); h[1] = __float2half_rn(a.y);
            h[2] = __float2half_rn(a.z); h[3] = __float2half_rn(a.w);
            h[4] = __float2half_rn(b.x); h[5] = __float2half_rn(b.y);
            h[6] = __float2half_rn(b.z); h[7] = __float2half_rn(b.w);
            *(uint4*)(o + (size_t)i * 8) = *(uint4*)h;
        }
    } else {
        for (int i = i0; i < GN * GD; i += stride) {
            const int row = i >> 8, col = i & 255;
            float s = 0.0f;
            const float* arow = adj + (size_t)row * GN;
            for (int k = 0; k < GN; k++) s += arow[k] * x[(size_t)k * GD + col];
            o[i] = __float2half_rn(x[i] + e * s);
        }
    }
}

// Between-layer fixup: if eps != 0, recompute fp16(x + eps*adj@x) from fp32.
__global__ void __launch_bounds__(256) agg_fix_kernel(
    const float* __restrict__ xin, const float* __restrict__ adj,
    const float* __restrict__ eps, __half* __restrict__ o) {
    const float e = eps[0];
    if (e == 0.0f) return;
    const int i0 = blockIdx.x * blockDim.x + threadIdx.x;
    const int stride = gridDim.x * blockDim.x;
    for (int i = i0; i < GN * GD; i += stride) {
        const int row = i >> 8, col = i & 255;
        float s = 0.0f;
        const float* arow = adj + (size_t)row * GN;
        for (int k = 0; k < GN; k++) s += arow[k] * xin[(size_t)k * GD + col];
        o[i] = __float2half_rn(xin[i] + e * s);
    }
}

// ---------------------------------------------------------------------------
// kernel_launch
// ---------------------------------------------------------------------------
extern "C" void kernel_launch(void* const* d_in, const int* in_sizes, int n_in,
                              void* d_out, int out_size) {
    const float* x   = (const float*)d_in[0];
    const float* adj = (const float*)d_in[1];
    const float* W1  = (const float*)d_in[2];
    const float* b1  = (const float*)d_in[3];
    const float* W2  = (const float*)d_in[4];
    const float* b2  = (const float*)d_in[5];
    const float* eps = (const float*)d_in[6];
    float* out = (float*)d_out;

    __half *A, *B, *W1h, *W2h;
    float* F;
    cudaGetSymbolAddress((void**)&A, g_A);
    cudaGetSymbolAddress((void**)&B, g_B);
    cudaGetSymbolAddress((void**)&W1h, g_W1);
    cudaGetSymbolAddress((void**)&W2h, g_W2);
    cudaGetSymbolAddress((void**)&F, g_F);

    cudaFuncSetAttribute(mlp_layer<false>,
                         cudaFuncAttributeMaxDynamicSharedMemorySize, SMEM_TOTAL);
    cudaFuncSetAttribute(mlp_layer<true>,
                         cudaFuncAttributeMaxDynamicSharedMemorySize, SMEM_TOTAL);

    // prep
    wconv_kernel<<<256, 256>>>(W1, W2, W1h, W2h);
    conv_agg_kernel<<<1184, 256>>>(x, adj, eps, A);

    // layer 1 (fused MLP): in A -> fp16 B (+ fp32 F if eps != 0)
    mlp_layer<false><<<GN / BM, 256, SMEM_TOTAL>>>(
        A, A, W1h, W2h, b1, b2, eps, B, F);

    // between layers: if eps != 0, recompute fp16 input from F into A
    agg_fix_kernel<<<512, 256>>>(F, adj, eps, A);

    // layer 2 (fused MLP): in (eps==0 ? B : A) -> fp32 out
    mlp_layer<true><<<GN / BM, 256, SMEM_TOTAL>>>(
        B, A, W1h, W2h, b1, b2, eps, nullptr, out);
}

// round 16
// speedup vs baseline: 1.8369x; 1.0722x over previous
#include <cuda_runtime.h>
#include <cuda_fp16.h>
#include <cstdint>

// GIN (N=8192, D=256), 2 layers. R16: 3 kernels total.
// Each fused layer kernel preps its own input in-prologue:
//   layer1: fp32 x -> fp16 smem (LDG convert, overlapped with W1 cp.async);
//           eps!=0 fallback computes x + eps*adj@x in-CTA.
//   layer2: fp16 B via cp.async; eps!=0 fallback computes from fp32 F.
// Phase1 H=relu(A@W1^T+b1) stays in smem; W slot reloaded with W2; phase2.
// Single-pass fp16 HMMA, fp32 accum.

#define GN 8192
#define GD 256

// ---------------- scratch (__device__ globals; no allocation allowed) ----------------
__device__ __half g_B[GN * GD];
__device__ __half g_W1[GD * GD];
__device__ __half g_W2[GD * GD];
__device__ float g_F[GN * GD];

// ---------------- PTX helpers (sm_80-era, compute_103-legal) ----------------
__device__ __forceinline__ uint32_t smem_u32(const void* p) {
    uint32_t a;
    asm("{ .reg .u64 t; cvta.to.shared.u64 t, %1; cvt.u32.u64 %0, t; }"
        : "=r"(a) : "l"(p));
    return a;
}

__device__ __forceinline__ void cp_async16(uint32_t s, const void* g) {
    asm volatile("cp.async.cg.shared.global [%0], [%1], 16;" :: "r"(s), "l"(g));
}
#define CP_COMMIT() asm volatile("cp.async.commit_group;" ::: "memory")
#define CP_WAIT(n)  asm volatile("cp.async.wait_group %0;" :: "n"(n) : "memory")

__device__ __forceinline__ void ldsm_x4(uint32_t* r, uint32_t addr) {
    asm volatile("ldmatrix.sync.aligned.m8n8.x4.shared.b16 {%0,%1,%2,%3}, [%4];"
                 : "=r"(r[0]), "=r"(r[1]), "=r"(r[2]), "=r"(r[3]) : "r"(addr));
}

__device__ __forceinline__ void mma16816(float* d, const uint32_t* a,
                                         const uint32_t* b) {
    asm volatile(
        "mma.sync.aligned.m16n8k16.row.col.f32.f16.f16.f32 "
        "{%0,%1,%2,%3}, {%4,%5,%6,%7}, {%8,%9}, {%0,%1,%2,%3};"
        : "+f"(d[0]), "+f"(d[1]), "+f"(d[2]), "+f"(d[3])
        : "r"(a[0]), "r"(a[1]), "r"(a[2]), "r"(a[3]), "r"(b[0]), "r"(b[1]));
}

// ---------------- tiling ----------------
#define BM 64
#define LDT 264                          // padded row stride (fp16)
#define LDTB (LDT * 2)                   // 528 bytes
#define A_BYTES (BM * LDTB)              // 33792
#define W_BYTES (GD * LDTB)              // 135168
#define OFF_A 0
#define OFF_W A_BYTES
#define OFF_H (A_BYTES + W_BYTES)        // 168960
#define SMEM_TOTAL (OFF_H + A_BYTES)     // 202752

struct FragP {
    uint32_t a[2][4];    // two m16 tiles
    uint32_t w[4][4];    // four n16 tiles (warp covers 64 N-cols)
};

// Fused layer: out = (relu(In@W1^T + b1))@W2^T + b2.
// grid 128; 256 thr = 8 warps in 2(m) x 4(n); warp tile 32x64.
// FIRST: input from fp32 xf (convert or agg). else: fp16 inh / fp32 srcF agg.
// LAST: write fp32 Of; else write fp16 Oh (+ fp32 Of when eps!=0).
template <bool FIRST, bool LAST>
__global__ void __launch_bounds__(256, 1)
mlp_layer(const float* __restrict__ xf, const __half* __restrict__ inh,
          const float* __restrict__ srcF, const float* __restrict__ adj,
          const __half* __restrict__ W1, const __half* __restrict__ W2,
          const float* __restrict__ b1, const float* __restrict__ b2,
          const float* __restrict__ eps,
          __half* __restrict__ Oh, float* __restrict__ Of) {
    extern __shared__ __align__(16) char smem[];
    const uint32_t sb = smem_u32(smem);
    const int tid = threadIdx.x;
    const int wid = tid >> 5;
    const int lane = tid & 31;
    const int warp_m = wid & 1;          // 2 warps along M (32 rows)
    const int warp_n = wid >> 1;         // 4 warps along N (64 cols)
    const int bm = blockIdx.x * BM;

    const float e = __ldg(eps);

    auto load_W_half = [&](const __half* W, int g) { // 256 rows x 128 cols
#pragma unroll
        for (int it = 0; it < 16; it++) {
            const int idx = tid + it * 256;          // 0..4095
            const int row = idx >> 4;
            const int q = idx & 15;
            cp_async16(sb + OFF_W + (uint32_t)(row * LDTB + g * 256 + q * 16),
                       W + (size_t)row * GD + g * 128 + q * 8);
        }
    };

    // ---------------- input prep (into A slot) ----------------
    // kick off W1 first so it streams while we prep A
    load_W_half(W1, 0); CP_COMMIT();
    load_W_half(W1, 1); CP_COMMIT();

    if (e == 0.0f) {
        if (FIRST) {
            // fp32 x -> fp16 smem A (LDG float4 x2 -> STS uint4)
            const float4* x4 = (const float4*)(xf + (size_t)bm * GD);
#pragma unroll
            for (int it = 0; it < 8; it++) {
                const int idx = tid + it * 256;      // 0..2047 (8-elem chunks)
                const int row = idx >> 5;
                const int q = idx & 31;
                float4 a = x4[(size_t)idx * 2];
                float4 b = x4[(size_t)idx * 2 + 1];
                __half h[8];
                h[0] = __float2half_rn(a.x); h[1] = __float2half_rn(a.y);
                h[2] = __float2half_rn(a.z); h[3] = __float2half_rn(a.w);
                h[4] = __float2half_rn(b.x); h[5] = __float2half_rn(b.y);
                h[6] = __float2half_rn(b.z); h[7] = __float2half_rn(b.w);
                *(uint4*)(smem + OFF_A + row * LDTB + q * 16) = *(uint4*)h;
            }
        } else {
            // fp16 in via LDG -> STS (keeps cp.async groups = W halves only)
            const uint4* i4 = (const uint4*)(inh + (size_t)bm * GD);
#pragma unroll
            for (int it = 0; it < 8; it++) {
                const int idx = tid + it * 256;      // 0..2047 (8-elem chunks)
                const int row = idx >> 5;
                const int q = idx & 31;
                *(uint4*)(smem + OFF_A + row * LDTB + q * 16) = i4[idx];
            }
        }
    } else {
        // fallback: recompute fp16(src + e * adj @ src) for this CTA's rows
        const float* src = FIRST ? xf : srcF;
        const int col = tid;                         // 256 threads = 256 cols
        for (int rr = 0; rr < BM; rr++) {
            const int row = bm + rr;
            float s = 0.0f;
            const float* arow = adj + (size_t)row * GN;
            for (int k = 0; k < GN; k++) s += arow[k] * src[(size_t)k * GD + col];
            const float v = src[(size_t)row * GD + col] + e * s;
            *(__half*)(smem + OFF_A + rr * LDTB + col * 2) = __float2half_rn(v);
        }
    }

    // ---- fragment addressing ----
    const uint32_t a_rel =
        (uint32_t)((warp_m * 32 + (lane & 15)) * LDTB) + (uint32_t)(lane >> 4) * 16;
    const int mmat = lane >> 3;
    const uint32_t w_rel =
        (uint32_t)((warp_n * 64 + (lane & 7) + ((mmat >> 1) & 1) * 8) * LDTB) +
        (uint32_t)(mmat & 1) * 16;

    float acc[2][8][4];

    auto ld_frags = [&](FragP& f, uint32_t abase, uint32_t wbase, int k16) {
        const uint32_t kadd = (uint32_t)k16 * 32;
#pragma unroll
        for (int mi = 0; mi < 2; mi++)
            ldsm_x4(f.a[mi], abase + a_rel + kadd + (uint32_t)(mi * 16 * LDTB));
#pragma unroll
        for (int ni = 0; ni < 4; ni++)
            ldsm_x4(f.w[ni], wbase + w_rel + kadd + (uint32_t)(ni * 16 * LDTB));
    };

    auto run8 = [&](uint32_t abase, uint32_t wbase, int k0) {
        FragP fr[2];
        ld_frags(fr[0], abase, wbase, k0);
#pragma unroll
        for (int i = 0; i < 8; i++) {
            const int cb = i & 1;
            if (i < 7) ld_frags(fr[cb ^ 1], abase, wbase, k0 + i + 1);
#pragma unroll
            for (int mi = 0; mi < 2; mi++)
#pragma unroll
                for (int n8 = 0; n8 < 8; n8++)
                    mma16816(acc[mi][n8], fr[cb].a[mi],
                             &fr[cb].w[n8 >> 1][(n8 & 1) * 2]);
        }
    };

#pragma unroll
    for (int i = 0; i < 2; i++)
#pragma unroll
        for (int j = 0; j < 8; j++)
#pragma unroll
            for (int k = 0; k < 4; k++) acc[i][j][k] = 0.0f;

    // ================= phase 1: H = relu(A @ W1^T + b1) =================
    CP_WAIT(1);                      // W1 lower k-half in
    __syncthreads();                 // + A stores visible
    run8(sb + OFF_A, sb + OFF_W, 0);
    CP_WAIT(0);
    __syncthreads();
    run8(sb + OFF_A, sb + OFF_W, 8);
    __syncthreads();                 // all warps done reading W1 / A

    // start W2 load into the W slot (overwrites W1)
    load_W_half(W2, 0); CP_COMMIT();
    load_W_half(W2, 1); CP_COMMIT();

    // store H (bias + relu + fp16) into smem H slot
    const int r = lane >> 2;
    const int c2 = (lane & 3) * 2;
#pragma unroll
    for (int mi = 0; mi < 2; mi++) {
#pragma unroll
        for (int half = 0; half < 2; half++) {
            const int rowl = warp_m * 32 + mi * 16 + r + half * 8;
#pragma unroll
            for (int n8 = 0; n8 < 8; n8++) {
                const int n = warp_n * 64 + n8 * 8 + c2;
                float v0 = acc[mi][n8][half * 2 + 0] + __ldg(b1 + n);
                float v1 = acc[mi][n8][half * 2 + 1] + __ldg(b1 + n + 1);
                v0 = fmaxf(v0, 0.0f);
                v1 = fmaxf(v1, 0.0f);
                __half2 hp;
                hp.x = __float2half_rn(v0);
                hp.y = __float2half_rn(v1);
                *(__half2*)(smem + OFF_H + rowl * LDTB + n * 2) = hp;
            }
        }
    }

#pragma unroll
    for (int i = 0; i < 2; i++)
#pragma unroll
        for (int j = 0; j < 8; j++)
#pragma unroll
            for (int k = 0; k < 4; k++) acc[i][j][k] = 0.0f;

    // ================= phase 2: out = H @ W2^T + b2 =================
    CP_WAIT(1);                      // W2 lower k-half in
    __syncthreads();                 // + H stores visible
    run8(sb + OFF_H, sb + OFF_W, 0);
    CP_WAIT(0);
    __syncthreads();
    run8(sb + OFF_H, sb + OFF_W, 8);

    // ---- epilogue ----
    const bool do_f32 = (!LAST) && (e != 0.0f);
#pragma unroll
    for (int mi = 0; mi < 2; mi++) {
#pragma unroll
        for (int half = 0; half < 2; half++) {
            const int m = bm + warp_m * 32 + mi * 16 + r + half * 8;
#pragma unroll
            for (int n8 = 0; n8 < 8; n8++) {
                const int n = warp_n * 64 + n8 * 8 + c2;
                float v0 = acc[mi][n8][half * 2 + 0] + __ldg(b2 + n);
                float v1 = acc[mi][n8][half * 2 + 1] + __ldg(b2 + n + 1);
                if (LAST) {
                    *(float2*)(Of + (size_t)m * GD + n) = make_float2(v0, v1);
                } else {
                    __half2 hp;
                    hp.x = __float2half_rn(v0);
                    hp.y = __float2half_rn(v1);
                    *(__half2*)(Oh + (size_t)m * GD + n) = hp;
                    if (do_f32)
                        *(float2*)(Of + (size_t)m * GD + n) = make_float2(v0, v1);
                }
            }
        }
    }
}

// ---------------------------------------------------------------------------
// Weight convert: W1,W2 fp32 -> fp16
// ---------------------------------------------------------------------------
__global__ void __launch_bounds__(256) wconv_kernel(
    const float* __restrict__ W1, const float* __restrict__ W2,
    __half* __restrict__ W1h, __half* __restrict__ W2h) {
    const int i = blockIdx.x * 256 + threadIdx.x;
    W1h[i] = __float2half_rn(W1[i]);
    W2h[i] = __float2half_rn(W2[i]);
}

// ---------------------------------------------------------------------------
// kernel_launch
// ---------------------------------------------------------------------------
extern "C" void kernel_launch(void* const* d_in, const int* in_sizes, int n_in,
                              void* d_out, int out_size) {
    const float* x   = (const float*)d_in[0];
    const float* adj = (const float*)d_in[1];
    const float* W1  = (const float*)d_in[2];
    const float* b1  = (const float*)d_in[3];
    const float* W2  = (const float*)d_in[4];
    const float* b2  = (const float*)d_in[5];
    const float* eps = (const float*)d_in[6];
    float* out = (float*)d_out;

    __half *B, *W1h, *W2h;
    float* F;
    cudaGetSymbolAddress((void**)&B, g_B);
    cudaGetSymbolAddress((void**)&W1h, g_W1);
    cudaGetSymbolAddress((void**)&W2h, g_W2);
    cudaGetSymbolAddress((void**)&F, g_F);

    cudaFuncSetAttribute(mlp_layer<true, false>,
                         cudaFuncAttributeMaxDynamicSharedMemorySize, SMEM_TOTAL);
    cudaFuncSetAttribute(mlp_layer<false, true>,
                         cudaFuncAttributeMaxDynamicSharedMemorySize, SMEM_TOTAL);

    // prep: weights fp32 -> fp16
    wconv_kernel<<<256, 256>>>(W1, W2, W1h, W2h);

    // layer 1: fp32 x in (convert/agg in-kernel) -> fp16 B (+ fp32 F if eps!=0)
    mlp_layer<true, false><<<GN / BM, 256, SMEM_TOTAL>>>(
        x, nullptr, nullptr, adj, W1h, W2h, b1, b2, eps, B, F);

    // layer 2: fp16 B in (or agg from F if eps!=0) -> fp32 out
    mlp_layer<false, true><<<GN / BM, 256, SMEM_TOTAL>>>(
        nullptr, B, F, adj, W1h, W2h, b1, b2, eps, nullptr, out);
}